// round 13
// baseline (speedup 1.0000x reference)
#include <cuda_runtime.h>
#include <cuda_bf16.h>
#include <cstdint>

// Problem constants
#define GRID_N   256
#define NB       1024
#define NH       32
#define NL       8
#define NS       8
#define BOUNDS_LO (-1.28f)
#define GRID_RES  (0.01f)
#define DIST_THR  (-0.01f)

__device__ __forceinline__ uint32_t smem_u32(const void* p) {
    uint32_t a;
    asm("{ .reg .u64 t; cvta.to.shared.u64 t, %1; cvt.u32.u64 %0, t; }"
        : "=r"(a) : "l"(p));
    return a;
}

// Two tiles per block, single wave (1024 blocks).
// Tile A: staged via per-thread __ldcs (R10 path, deferred-blocking sync).
// Tile B: prefetched via cp.async.bulk at block start; its DMA overlaps all of
// tile A's gather work, so the mbarrier wait is a completed fast-path.
// Gathers: ld.global.cg (L2-only). Numerics bit-identical to R10.
__global__ __launch_bounds__(256, 8)
void voxel_collision_kernel(const float* __restrict__ link_pos,   // [B,H,L,3]
                            const float* __restrict__ link_rot,   // [B,H,L,3,3]
                            const float* __restrict__ sph_ctr,    // [L,S,3]
                            const float* __restrict__ sph_rad,    // [L,S]
                            const float* __restrict__ sdf,        // [256^3]
                            const float* __restrict__ weight,     // scalar
                            float* __restrict__ out)              // [B,H]
{
    __shared__ alignas(16) float s_rotA[128 * 9];     // 4608 B
    __shared__ alignas(16) float s_posA[128 * 3];     // 1536 B
    __shared__ alignas(16) float s_rotB[128 * 9];     // 4608 B (bulk dst)
    __shared__ alignas(16) float s_posB[128 * 3];     // 1536 B (bulk dst)
    __shared__ alignas(16) float s_ctr[NL * NS * 3];  // 768 B
    __shared__ alignas(16) float s_rad[NL * NS];      // 256 B
    __shared__ alignas(8)  unsigned long long s_mbar;

    const int tileA = blockIdx.x;            // 0..1023
    const int tileB = blockIdx.x + 1024;     // 1024..2047
    const uint32_t mbar = smem_u32(&s_mbar);

    // Thread 0: kick off tile B's pose prefetch through the async proxy.
    if (threadIdx.x == 0) {
        asm volatile("mbarrier.init.shared.b64 [%0], %1;"
                     :: "r"(mbar), "r"(1) : "memory");
        asm volatile("mbarrier.arrive.expect_tx.shared.b64 _, [%0], %1;"
                     :: "r"(mbar), "r"(6144u) : "memory");
        asm volatile("cp.async.bulk.shared::cluster.global.mbarrier::complete_tx::bytes [%0], [%1], %2, [%3];"
                     :: "r"(smem_u32(s_rotB)),
                        "l"(link_rot + (size_t)tileB * 1152),
                        "r"(4608u), "r"(mbar) : "memory");
        asm volatile("cp.async.bulk.shared::cluster.global.mbarrier::complete_tx::bytes [%0], [%1], %2, [%3];"
                     :: "r"(smem_u32(s_posB)),
                        "l"(link_pos + (size_t)tileB * 384),
                        "r"(1536u), "r"(mbar) : "memory");
    }

    // Tile A staging, R10 style (coalesced streaming loads).
    {
        const float4* g4 = (const float4*)(link_rot + (size_t)tileA * 1152);
        float4* s4 = (float4*)s_rotA;
        #pragma unroll
        for (int i = threadIdx.x; i < 288; i += 256) s4[i] = __ldcs(&g4[i]);

        const float4* p4 = (const float4*)(link_pos + (size_t)tileA * 384);
        float4* sp4 = (float4*)s_posA;
        if (threadIdx.x < 96) sp4[threadIdx.x] = __ldcs(&p4[threadIdx.x]);

        if (threadIdx.x < NL * NS * 3) s_ctr[threadIdx.x] = sph_ctr[threadIdx.x];
        if (threadIdx.x < NL * NS)     s_rad[threadIdx.x] = sph_rad[threadIdx.x];
    }
    __syncthreads();   // also orders mbarrier.init before any try_wait below

    const int u  = threadIdx.x >> 1;         // local (b,h,l) unit 0..127
    const int l  = u & (NL - 1);             // link id (tile is 8-aligned)
    const int sb = (threadIdx.x & 1) * 4;    // sphere base: 0 or 4
    const unsigned mask = 0xFFFFFFFFu;

    // sphere constants (shared by both tiles)
    float cx[4], cy[4], cz[4], rad[4];
    #pragma unroll
    for (int s = 0; s < 4; s++) {
        const float* c = &s_ctr[(l * NS + sb + s) * 3];
        cx[s] = c[0]; cy[s] = c[1]; cz[s] = c[2];
        rad[s] = s_rad[l * NS + sb + s];
    }

    const float w = __ldg(weight);

    // ================= tile A =================
    {
        const float r00 = s_rotA[u*9+0], r01 = s_rotA[u*9+1], r02 = s_rotA[u*9+2];
        const float r10 = s_rotA[u*9+3], r11 = s_rotA[u*9+4], r12 = s_rotA[u*9+5];
        const float r20 = s_rotA[u*9+6], r21 = s_rotA[u*9+7], r22 = s_rotA[u*9+8];
        const float px = s_posA[u*3+0], py = s_posA[u*3+1], pz = s_posA[u*3+2];

        float sval[4];
        #pragma unroll
        for (int s = 0; s < 4; s++) {
            float x = __fadd_rn(__fadd_rn(__fadd_rn(__fmul_rn(r00, cx[s]), __fmul_rn(r01, cy[s])), __fmul_rn(r02, cz[s])), px);
            float y = __fadd_rn(__fadd_rn(__fadd_rn(__fmul_rn(r10, cx[s]), __fmul_rn(r11, cy[s])), __fmul_rn(r12, cz[s])), py);
            float z = __fadd_rn(__fadd_rn(__fadd_rn(__fmul_rn(r20, cx[s]), __fmul_rn(r21, cy[s])), __fmul_rn(r22, cz[s])), pz);
            int ix = (int)floorf(__fdiv_rn(__fsub_rn(x, BOUNDS_LO), GRID_RES));
            int iy = (int)floorf(__fdiv_rn(__fsub_rn(y, BOUNDS_LO), GRID_RES));
            int iz = (int)floorf(__fdiv_rn(__fsub_rn(z, BOUNDS_LO), GRID_RES));
            ix = min(max(ix, 0), GRID_N - 1);
            iy = min(max(iy, 0), GRID_N - 1);
            iz = min(max(iz, 0), GRID_N - 1);
            sval[s] = __ldcg(&sdf[((ix * GRID_N) + iy) * GRID_N + iz]);
        }

        float m = -1e30f;
        #pragma unroll
        for (int s = 0; s < 4; s++) m = fmaxf(m, rad[s] - sval[s]);
        m = fmaxf(m, __shfl_xor_sync(mask, m, 1));

        float res = fminf(fmaxf(m + DIST_THR, 0.0f), 0.5f) * 4.0f;
        res += __shfl_down_sync(mask, res, 2);
        res += __shfl_down_sync(mask, res, 4);
        res += __shfl_down_sync(mask, res, 8);

        if ((threadIdx.x & 15) == 0)
            out[tileA * 16 + (threadIdx.x >> 4)] = w * res;
    }

    // ================= tile B (prefetch completed long ago) =================
    {
        uint32_t done;
        asm volatile(
            "{\n\t"
            ".reg .pred p;\n\t"
            "mbarrier.try_wait.parity.acquire.cta.shared::cta.b64 p, [%1], %2;\n\t"
            "selp.b32 %0, 1, 0, p;\n\t"
            "}"
            : "=r"(done) : "r"(mbar), "r"(0) : "memory");
        if (!done) {
            asm volatile(
                "{\n\t"
                ".reg .pred P1;\n\t"
                "WAIT_LOOP:\n\t"
                "mbarrier.try_wait.parity.acquire.cta.shared::cta.b64 P1, [%0], %1, 0x989680;\n\t"
                "@P1 bra.uni WAIT_DONE;\n\t"
                "bra.uni WAIT_LOOP;\n\t"
                "WAIT_DONE:\n\t"
                "}"
                :: "r"(mbar), "r"(0) : "memory");
        }

        const float r00 = s_rotB[u*9+0], r01 = s_rotB[u*9+1], r02 = s_rotB[u*9+2];
        const float r10 = s_rotB[u*9+3], r11 = s_rotB[u*9+4], r12 = s_rotB[u*9+5];
        const float r20 = s_rotB[u*9+6], r21 = s_rotB[u*9+7], r22 = s_rotB[u*9+8];
        const float px = s_posB[u*3+0], py = s_posB[u*3+1], pz = s_posB[u*3+2];

        float sval[4];
        #pragma unroll
        for (int s = 0; s < 4; s++) {
            float x = __fadd_rn(__fadd_rn(__fadd_rn(__fmul_rn(r00, cx[s]), __fmul_rn(r01, cy[s])), __fmul_rn(r02, cz[s])), px);
            float y = __fadd_rn(__fadd_rn(__fadd_rn(__fmul_rn(r10, cx[s]), __fmul_rn(r11, cy[s])), __fmul_rn(r12, cz[s])), py);
            float z = __fadd_rn(__fadd_rn(__fadd_rn(__fmul_rn(r20, cx[s]), __fmul_rn(r21, cy[s])), __fmul_rn(r22, cz[s])), pz);
            int ix = (int)floorf(__fdiv_rn(__fsub_rn(x, BOUNDS_LO), GRID_RES));
            int iy = (int)floorf(__fdiv_rn(__fsub_rn(y, BOUNDS_LO), GRID_RES));
            int iz = (int)floorf(__fdiv_rn(__fsub_rn(z, BOUNDS_LO), GRID_RES));
            ix = min(max(ix, 0), GRID_N - 1);
            iy = min(max(iy, 0), GRID_N - 1);
            iz = min(max(iz, 0), GRID_N - 1);
            sval[s] = __ldcg(&sdf[((ix * GRID_N) + iy) * GRID_N + iz]);
        }

        float m = -1e30f;
        #pragma unroll
        for (int s = 0; s < 4; s++) m = fmaxf(m, rad[s] - sval[s]);
        m = fmaxf(m, __shfl_xor_sync(mask, m, 1));

        float res = fminf(fmaxf(m + DIST_THR, 0.0f), 0.5f) * 4.0f;
        res += __shfl_down_sync(mask, res, 2);
        res += __shfl_down_sync(mask, res, 4);
        res += __shfl_down_sync(mask, res, 8);

        if ((threadIdx.x & 15) == 0)
            out[tileB * 16 + (threadIdx.x >> 4)] = w * res;
    }
}

extern "C" void kernel_launch(void* const* d_in, const int* in_sizes, int n_in,
                              void* d_out, int out_size)
{
    const float* link_pos = (const float*)d_in[0];  // [1024,32,8,3]
    const float* link_rot = (const float*)d_in[1];  // [1024,32,8,3,3]
    const float* sph_ctr  = (const float*)d_in[2];  // [8,8,3]
    const float* sph_rad  = (const float*)d_in[3];  // [8,8]
    const float* sdf      = (const float*)d_in[4];  // [256,256,256]
    const float* weight   = (const float*)d_in[5];  // scalar
    float* out = (float*)d_out;                     // [1024,32]

    // 1024 blocks (single wave), 2 tiles of 128 units per block.
    voxel_collision_kernel<<<1024, 256>>>(link_pos, link_rot, sph_ctr,
                                          sph_rad, sdf, weight, out);
}

// round 14
// speedup vs baseline: 1.2548x; 1.2548x over previous
#include <cuda_runtime.h>
#include <cuda_bf16.h>
#include <cstdint>

// Problem constants
#define GRID_N   256
#define NB       1024
#define NH       32
#define NL       8
#define NS       8
#define BOUNDS_LO (-1.28f)
#define GRID_RES  (0.01f)
#define DIST_THR  (-0.01f)

// 2 threads per (b,h,l): each handles 4 spheres (MLP=4), 524288 threads total.
// Gathers use ld.global.cg (L2-only, no L1 allocation): gather hit rate in L1
// is <1%, so skipping L1 line allocation removes tag churn from the replay
// path. Pose staging stays streaming (evict-first).
//
// Converged configuration (best of 12 measured variants, 14.82us):
//  - MLP=4 per thread (4 and only 4 front-batched gathers; 8 triggers
//    cross-CTA L1tex-queue spread, 2 under-covers latency)
//  - 2048 blocks x 256 threads, occ ~85% (more occupancy gave no speedup;
//    kernel sits on the L1tex divergent-gather replay floor)
//  - pose data staged through shared via coalesced streaming float4 loads
//  - index math: mul-then-add round-to-nearest + __fdiv_rn (rel_err 1.95e-4)
__global__ __launch_bounds__(256, 8)
void voxel_collision_kernel(const float* __restrict__ link_pos,   // [B,H,L,3]
                            const float* __restrict__ link_rot,   // [B,H,L,3,3]
                            const float* __restrict__ sph_ctr,    // [L,S,3]
                            const float* __restrict__ sph_rad,    // [L,S]
                            const float* __restrict__ sdf,        // [256^3]
                            const float* __restrict__ weight,     // scalar
                            float* __restrict__ out)              // [B,H]
{
    // Block covers 128 (b,h,l) units.
    __shared__ float s_rot[128 * 9];       // 1152 floats
    __shared__ float s_pos[128 * 3];       // 384 floats
    __shared__ float s_ctr[NL * NS * 3];   // 192 floats
    __shared__ float s_rad[NL * NS];       // 64 floats

    // Coalesced, streaming staging of this block's pose data.
    {
        const float4* g4 = (const float4*)(link_rot + (size_t)blockIdx.x * 1152);
        float4* s4 = (float4*)s_rot;
        #pragma unroll
        for (int i = threadIdx.x; i < 288; i += 256) s4[i] = __ldcs(&g4[i]);

        const float4* p4 = (const float4*)(link_pos + (size_t)blockIdx.x * 384);
        float4* sp4 = (float4*)s_pos;
        if (threadIdx.x < 96) sp4[threadIdx.x] = __ldcs(&p4[threadIdx.x]);

        if (threadIdx.x < NL * NS * 3) s_ctr[threadIdx.x] = sph_ctr[threadIdx.x];
        if (threadIdx.x < NL * NS)     s_rad[threadIdx.x] = sph_rad[threadIdx.x];
    }
    __syncthreads();

    const int u  = threadIdx.x >> 1;         // local (b,h,l) unit 0..127
    const int l  = u & (NL - 1);             // link id (block is 8-aligned)
    const int sb = (threadIdx.x & 1) * 4;    // sphere base: 0 or 4

    const float r00 = s_rot[u * 9 + 0], r01 = s_rot[u * 9 + 1], r02 = s_rot[u * 9 + 2];
    const float r10 = s_rot[u * 9 + 3], r11 = s_rot[u * 9 + 4], r12 = s_rot[u * 9 + 5];
    const float r20 = s_rot[u * 9 + 6], r21 = s_rot[u * 9 + 7], r22 = s_rot[u * 9 + 8];
    const float px = s_pos[u * 3 + 0], py = s_pos[u * 3 + 1], pz = s_pos[u * 3 + 2];

    // 4 gather addresses computed back-to-back, then 4 independent loads.
    float sval[4];
    #pragma unroll
    for (int s = 0; s < 4; s++) {
        const float* c = &s_ctr[(l * NS + sb + s) * 3];
        const float cx = c[0], cy = c[1], cz = c[2];
        // mul-then-add, round-to-nearest, no FMA contraction (bit-identical to
        // the passing rounds' numerics; rel_err 1.95e-4).
        float x = __fadd_rn(__fadd_rn(__fadd_rn(__fmul_rn(r00, cx), __fmul_rn(r01, cy)), __fmul_rn(r02, cz)), px);
        float y = __fadd_rn(__fadd_rn(__fadd_rn(__fmul_rn(r10, cx), __fmul_rn(r11, cy)), __fmul_rn(r12, cz)), py);
        float z = __fadd_rn(__fadd_rn(__fadd_rn(__fmul_rn(r20, cx), __fmul_rn(r21, cy)), __fmul_rn(r22, cz)), pz);

        int ix = (int)floorf(__fdiv_rn(__fsub_rn(x, BOUNDS_LO), GRID_RES));
        int iy = (int)floorf(__fdiv_rn(__fsub_rn(y, BOUNDS_LO), GRID_RES));
        int iz = (int)floorf(__fdiv_rn(__fsub_rn(z, BOUNDS_LO), GRID_RES));
        ix = min(max(ix, 0), GRID_N - 1);
        iy = min(max(iy, 0), GRID_N - 1);
        iz = min(max(iz, 0), GRID_N - 1);
        sval[s] = __ldcg(&sdf[((ix * GRID_N) + iy) * GRID_N + iz]);
    }

    const float w = __ldg(weight);           // off the critical path

    // worst penetration over this thread's 4 spheres
    float m = -1e30f;
    #pragma unroll
    for (int s = 0; s < 4; s++)
        m = fmaxf(m, s_rad[l * NS + sb + s] - sval[s]);

    // combine the two half-threads of this link (adjacent lanes)
    const unsigned mask = 0xFFFFFFFFu;
    m = fmaxf(m, __shfl_xor_sync(mask, m, 1));

    // threshold / clamp / normalize:  clip(m - 0.01, 0, 0.5) / 0.25
    float res = m + DIST_THR;
    res = fminf(fmaxf(res, 0.0f), 0.5f) * 4.0f;

    // sum 8 links of one (b,h): lanes [16k .. 16k+15], one value per lane pair.
    res += __shfl_down_sync(mask, res, 2);
    res += __shfl_down_sync(mask, res, 4);
    res += __shfl_down_sync(mask, res, 8);

    if ((threadIdx.x & 15) == 0) {
        out[(blockIdx.x * 256 + threadIdx.x) >> 4] = w * res;
    }
}

extern "C" void kernel_launch(void* const* d_in, const int* in_sizes, int n_in,
                              void* d_out, int out_size)
{
    const float* link_pos = (const float*)d_in[0];  // [1024,32,8,3]
    const float* link_rot = (const float*)d_in[1];  // [1024,32,8,3,3]
    const float* sph_ctr  = (const float*)d_in[2];  // [8,8,3]
    const float* sph_rad  = (const float*)d_in[3];  // [8,8]
    const float* sdf      = (const float*)d_in[4];  // [256,256,256]
    const float* weight   = (const float*)d_in[5];  // scalar
    float* out = (float*)d_out;                     // [1024,32]

    const int total = NB * NH * NL * 2;             // 524288 threads
    voxel_collision_kernel<<<total / 256, 256>>>(link_pos, link_rot, sph_ctr,
                                                 sph_rad, sdf, weight, out);
}